// round 1
// baseline (speedup 1.0000x reference)
#include <cuda_runtime.h>
#include <math.h>

#define EPSV 1e-8f
#define D 512
#define BM 128
#define BN 128
#define BK 16
#define TM 8
#define TN 8

// Scratch for row norms (allocation-free: __device__ globals)
__device__ float g_norm1[8192];  // norms of x1 rows (n-dim)
__device__ float g_norm2[8192];  // norms of x2 rows (m-dim)

// One block per row; 128 threads, each reads one float4 (512 floats/row).
__global__ void norms_kernel(const float* __restrict__ x1,
                             const float* __restrict__ x2,
                             int N, int M) {
    int r = blockIdx.x;
    const float* x;
    float* o;
    int row;
    if (r < N) { x = x1; o = g_norm1; row = r; }
    else       { x = x2; o = g_norm2; row = r - N; }

    const float4* p = reinterpret_cast<const float4*>(x + (size_t)row * D);
    float4 v = p[threadIdx.x];
    float s = v.x * v.x + v.y * v.y + v.z * v.z + v.w * v.w;
    #pragma unroll
    for (int off = 16; off > 0; off >>= 1)
        s += __shfl_down_sync(0xffffffffu, s, off);
    __shared__ float ws[4];
    int w = threadIdx.x >> 5;
    if ((threadIdx.x & 31) == 0) ws[w] = s;
    __syncthreads();
    if (threadIdx.x == 0)
        o[row] = sqrtf(ws[0] + ws[1] + ws[2] + ws[3]);
}

// C[m][n] = dot(A_row m, B_row n) / max(nA[m]*nB[n], eps)
// A = x2 [M, 512], B = x1 [N, 512], C = [M, N]
__global__ __launch_bounds__(256, 2)
void cosine_gemm_kernel(const float* __restrict__ A,
                        const float* __restrict__ B,
                        float* __restrict__ C,
                        int Ncols) {
    __shared__ __align__(16) float As[BK][BM];
    __shared__ __align__(16) float Bs[BK][BN];

    const int bm = blockIdx.y * BM;
    const int bn = blockIdx.x * BN;
    const int tid = threadIdx.x;
    const int tx = tid & 15;   // n direction (16)
    const int ty = tid >> 4;   // m direction (16)

    // f32x2 packed accumulators: 8 m-rows x 4 n-pairs
    unsigned long long acc[TM][TN / 2];
    #pragma unroll
    for (int i = 0; i < TM; i++)
        #pragma unroll
        for (int j = 0; j < TN / 2; j++)
            acc[i][j] = 0ull;

    const float* Ab = A + (size_t)bm * D;
    const float* Bb = B + (size_t)bn * D;

    for (int k0 = 0; k0 < D; k0 += BK) {
        // Load 128x16 tiles of A and B, transposed into [k][m] layout.
        // 512 float4 per tile / 256 threads = 2 float4 each per operand.
        #pragma unroll
        for (int l = 0; l < 2; l++) {
            int id  = tid + l * 256;
            int row = id >> 2;
            int c4  = id & 3;
            float4 va = *reinterpret_cast<const float4*>(Ab + (size_t)row * D + k0 + c4 * 4);
            As[c4 * 4 + 0][row] = va.x;
            As[c4 * 4 + 1][row] = va.y;
            As[c4 * 4 + 2][row] = va.z;
            As[c4 * 4 + 3][row] = va.w;
            float4 vb = *reinterpret_cast<const float4*>(Bb + (size_t)row * D + k0 + c4 * 4);
            Bs[c4 * 4 + 0][row] = vb.x;
            Bs[c4 * 4 + 1][row] = vb.y;
            Bs[c4 * 4 + 2][row] = vb.z;
            Bs[c4 * 4 + 3][row] = vb.w;
        }
        __syncthreads();

        #pragma unroll
        for (int kk = 0; kk < BK; kk++) {
            float4 a0 = *reinterpret_cast<const float4*>(&As[kk][ty * TM]);
            float4 a1 = *reinterpret_cast<const float4*>(&As[kk][ty * TM + 4]);
            float4 b0 = *reinterpret_cast<const float4*>(&Bs[kk][tx * TN]);
            float4 b1 = *reinterpret_cast<const float4*>(&Bs[kk][tx * TN + 4]);

            float a[TM] = {a0.x, a0.y, a0.z, a0.w, a1.x, a1.y, a1.z, a1.w};
            unsigned long long b2[TN / 2];
            asm("mov.b64 %0, {%1, %2};" : "=l"(b2[0]) : "f"(b0.x), "f"(b0.y));
            asm("mov.b64 %0, {%1, %2};" : "=l"(b2[1]) : "f"(b0.z), "f"(b0.w));
            asm("mov.b64 %0, {%1, %2};" : "=l"(b2[2]) : "f"(b1.x), "f"(b1.y));
            asm("mov.b64 %0, {%1, %2};" : "=l"(b2[3]) : "f"(b1.z), "f"(b1.w));

            #pragma unroll
            for (int i = 0; i < TM; i++) {
                unsigned long long aa;
                asm("mov.b64 %0, {%1, %1};" : "=l"(aa) : "f"(a[i]));
                #pragma unroll
                for (int j = 0; j < TN / 2; j++) {
                    asm("fma.rn.f32x2 %0, %1, %2, %0;"
                        : "+l"(acc[i][j]) : "l"(aa), "l"(b2[j]));
                }
            }
        }
        __syncthreads();
    }

    // Epilogue: divide by max(norm product, eps), vectorized stores.
    float nb[TN];
    #pragma unroll
    for (int j = 0; j < TN; j++)
        nb[j] = g_norm1[bn + tx * TN + j];

    #pragma unroll
    for (int i = 0; i < TM; i++) {
        int m = bm + ty * TM + i;
        float na = g_norm2[m];
        float vals[TN];
        #pragma unroll
        for (int j = 0; j < TN / 2; j++) {
            float lo, hi;
            asm("mov.b64 {%0, %1}, %2;" : "=f"(lo), "=f"(hi) : "l"(acc[i][j]));
            vals[2 * j]     = lo;
            vals[2 * j + 1] = hi;
        }
        #pragma unroll
        for (int j = 0; j < TN; j++)
            vals[j] = __fdividef(vals[j], fmaxf(na * nb[j], EPSV));

        float4* cp = reinterpret_cast<float4*>(C + (size_t)m * Ncols + bn + tx * TN);
        cp[0] = make_float4(vals[0], vals[1], vals[2], vals[3]);
        cp[1] = make_float4(vals[4], vals[5], vals[6], vals[7]);
    }
}

extern "C" void kernel_launch(void* const* d_in, const int* in_sizes, int n_in,
                              void* d_out, int out_size) {
    const float* x1 = (const float*)d_in[0];  // [N, 512]
    const float* x2 = (const float*)d_in[1];  // [M, 512]
    float* out = (float*)d_out;               // [M, N]

    int N = in_sizes[0] / D;  // 8192
    int M = in_sizes[1] / D;  // 8192

    norms_kernel<<<N + M, 128>>>(x1, x2, N, M);

    dim3 grid(N / BN, M / BM);
    cosine_gemm_kernel<<<grid, 256>>>(x2, x1, out, N);
}

// round 3
// speedup vs baseline: 2.4344x; 2.4344x over previous
#include <cuda_runtime.h>
#include <cuda_bf16.h>
#include <stdint.h>
#include <math.h>

#define EPSV 1e-8f
#define DD 512
#define MR 8192
#define NR 8192
#define BM 128
#define BN 128
#define BK 32            // bf16 elements per k-step
#define PADK 40          // padded smem row length (80 B) -> conflict-free ldmatrix
#define STAGES 3
#define KSTEPS 16        // 512 / 32 per pass
#define SSTEPS 48        // 3 passes (hh, hl, lh)

// ---------------- device scratch (allocation-free) ----------------
__device__ __nv_bfloat16 g_ah[(size_t)MR * DD];
__device__ __nv_bfloat16 g_al[(size_t)MR * DD];
__device__ __nv_bfloat16 g_bh[(size_t)NR * DD];
__device__ __nv_bfloat16 g_bl[(size_t)NR * DD];
__device__ float g_na[MR];
__device__ float g_nb[NR];

__device__ __forceinline__ uint32_t smem_u32(const void* p) {
    uint32_t a;
    asm("{ .reg .u64 t; cvta.to.shared.u64 t, %1; cvt.u32.u64 %0, t; }" : "=r"(a) : "l"(p));
    return a;
}

#define CP16(dst, src) \
    asm volatile("cp.async.cg.shared.global [%0], [%1], 16;" :: "r"(dst), "l"(src))
#define CP_COMMIT() asm volatile("cp.async.commit_group;" ::: "memory")
#define CP_WAIT1()  asm volatile("cp.async.wait_group 1;" ::: "memory")

#define LDSM_X4(r0, r1, r2, r3, addr) \
    asm volatile("ldmatrix.sync.aligned.m8n8.x4.shared.b16 {%0,%1,%2,%3}, [%4];" \
                 : "=r"(r0), "=r"(r1), "=r"(r2), "=r"(r3) : "r"(addr))

#define MMA16816(d, a, b0, b1) \
    asm volatile("mma.sync.aligned.m16n8k16.row.col.f32.bf16.bf16.f32 " \
                 "{%0,%1,%2,%3}, {%4,%5,%6,%7}, {%8,%9}, {%0,%1,%2,%3};" \
                 : "+f"((d)[0]), "+f"((d)[1]), "+f"((d)[2]), "+f"((d)[3]) \
                 : "r"((a)[0]), "r"((a)[1]), "r"((a)[2]), "r"((a)[3]), "r"(b0), "r"(b1))

// ---------------- prep: fp32 -> bf16 hi/lo + row norms ----------------
__global__ void prep_kernel(const float* __restrict__ x1, const float* __restrict__ x2) {
    int r = blockIdx.x;
    const float* src;
    __nv_bfloat16 *hi, *lo;
    float* nrm;
    int row;
    if (r < NR) { src = x1; hi = g_bh; lo = g_bl; nrm = g_nb; row = r; }
    else        { src = x2; hi = g_ah; lo = g_al; nrm = g_na; row = r - NR; }

    const float4* p = reinterpret_cast<const float4*>(src + (size_t)row * DD);
    float4 v = p[threadIdx.x];
    float vv[4] = {v.x, v.y, v.z, v.w};
    float s = v.x * v.x + v.y * v.y + v.z * v.z + v.w * v.w;

    __nv_bfloat16 h[4], l[4];
#pragma unroll
    for (int i = 0; i < 4; i++) {
        h[i] = __float2bfloat16(vv[i]);
        l[i] = __float2bfloat16(vv[i] - __bfloat162float(h[i]));
    }
    size_t o = (size_t)row * DD + threadIdx.x * 4;
    *reinterpret_cast<__nv_bfloat162*>(hi + o)     = __halves2bfloat162(h[0], h[1]);
    *reinterpret_cast<__nv_bfloat162*>(hi + o + 2) = __halves2bfloat162(h[2], h[3]);
    *reinterpret_cast<__nv_bfloat162*>(lo + o)     = __halves2bfloat162(l[0], l[1]);
    *reinterpret_cast<__nv_bfloat162*>(lo + o + 2) = __halves2bfloat162(l[2], l[3]);

#pragma unroll
    for (int off = 16; off > 0; off >>= 1)
        s += __shfl_down_sync(0xffffffffu, s, off);
    __shared__ float ws[4];
    if ((threadIdx.x & 31) == 0) ws[threadIdx.x >> 5] = s;
    __syncthreads();
    if (threadIdx.x == 0)
        nrm[row] = sqrtf(ws[0] + ws[1] + ws[2] + ws[3]);
}

// ---------------- GEMM via mma.sync (HMMA) + cosine epilogue ----------------
// Dynamic smem: STAGES stages, each [BM][PADK] A + [BN][PADK] B bf16.
#define STAGE_ELEMS ((BM + BN) * PADK)

__device__ __forceinline__ void load_stage(uint32_t sbase, int stage, int s,
                                           int bm, int bn, int tid) {
    const int pass = s >> 4;
    const int ko = (s & 15) * BK;
    const __nv_bfloat16* Ap = (pass == 2) ? g_al : g_ah;
    const __nv_bfloat16* Bp = (pass == 1) ? g_bl : g_bh;
    uint32_t abase = sbase + stage * STAGE_ELEMS * 2;
    uint32_t bbase = abase + BM * PADK * 2;
#pragma unroll
    for (int h = 0; h < 2; h++) {
        int c = tid + h * 256;
        int row = c >> 2, seg = c & 3;
        uint32_t dst = abase + (uint32_t)(row * PADK + seg * 8) * 2;
        CP16(dst, Ap + (size_t)(bm + row) * DD + ko + seg * 8);
    }
#pragma unroll
    for (int h = 0; h < 2; h++) {
        int c = tid + h * 256;
        int row = c >> 2, seg = c & 3;
        uint32_t dst = bbase + (uint32_t)(row * PADK + seg * 8) * 2;
        CP16(dst, Bp + (size_t)(bn + row) * DD + ko + seg * 8);
    }
    CP_COMMIT();
}

__global__ void __launch_bounds__(256, 2)
cosine_mma_kernel(float* __restrict__ C) {
    extern __shared__ __align__(16) __nv_bfloat16 smem[];
    const uint32_t sbase = smem_u32(smem);
    const int tid = threadIdx.x;
    const int wid = tid >> 5;
    const int lid = tid & 31;
    const int bm = blockIdx.y * BM;
    const int bn = blockIdx.x * BN;

    __shared__ float s_na[BM], s_nb[BN];
    if (tid < BM) s_na[tid] = g_na[bm + tid];
    else s_nb[tid - BM] = g_nb[bn + tid - BM];

    const int wm = (wid & 1) * 64;   // warp m-base within tile
    const int wn = (wid >> 1) * 32;  // warp n-base within tile

    float acc[4][4][4];
#pragma unroll
    for (int i = 0; i < 4; i++)
#pragma unroll
        for (int j = 0; j < 4; j++)
#pragma unroll
            for (int q = 0; q < 4; q++)
                acc[i][j][q] = 0.0f;

    // ldmatrix lane-address components (constant across k-steps)
    const int a_row = wm + ((lid >> 3) & 1) * 8 + (lid & 7);
    const int a_kof = ((lid >> 4) & 1) * 8;
    const int b_row = wn + ((lid >> 4) & 1) * 8 + (lid & 7);
    const int b_kof = ((lid >> 3) & 1) * 8;

    // prologue
    load_stage(sbase, 0, 0, bm, bn, tid);
    load_stage(sbase, 1, 1, bm, bn, tid);

    for (int s = 0; s < SSTEPS; s++) {
        const int stage = s % STAGES;
        CP_WAIT1();
        __syncthreads();

        uint32_t abase = sbase + stage * STAGE_ELEMS * 2;
        uint32_t bbase = abase + BM * PADK * 2;

#pragma unroll
        for (int k16 = 0; k16 < BK / 16; k16++) {
            const int k0 = k16 * 16;
            uint32_t a[4][4];
#pragma unroll
            for (int mi = 0; mi < 4; mi++) {
                uint32_t addr = abase + (uint32_t)((a_row + mi * 16) * PADK + k0 + a_kof) * 2;
                LDSM_X4(a[mi][0], a[mi][1], a[mi][2], a[mi][3], addr);
            }
            uint32_t b[2][4];
#pragma unroll
            for (int nj = 0; nj < 2; nj++) {
                uint32_t addr = bbase + (uint32_t)((b_row + nj * 16) * PADK + k0 + b_kof) * 2;
                LDSM_X4(b[nj][0], b[nj][1], b[nj][2], b[nj][3], addr);
            }
#pragma unroll
            for (int mi = 0; mi < 4; mi++)
#pragma unroll
                for (int ni = 0; ni < 4; ni++)
                    MMA16816(acc[mi][ni], a[mi], b[ni >> 1][(ni & 1) * 2],
                             b[ni >> 1][(ni & 1) * 2 + 1]);
        }
        __syncthreads();
        if (s + STAGES - 1 < SSTEPS)
            load_stage(sbase, (s + STAGES - 1) % STAGES, s + STAGES - 1, bm, bn, tid);
    }

    // epilogue: cosine divide + store
    const int qrow = lid >> 2;      // 0..7
    const int qcol = (lid & 3) * 2; // 0,2,4,6
#pragma unroll
    for (int mi = 0; mi < 4; mi++) {
        int m0 = wm + mi * 16 + qrow;
        float na0 = s_na[m0];
        float na1 = s_na[m0 + 8];
        float* r0 = C + (size_t)(bm + m0) * NR + bn;
        float* r1 = C + (size_t)(bm + m0 + 8) * NR + bn;
#pragma unroll
        for (int ni = 0; ni < 4; ni++) {
            int n0 = wn + ni * 8 + qcol;
            float nb0 = s_nb[n0], nb1 = s_nb[n0 + 1];
            float2 v0, v1;
            v0.x = __fdividef(acc[mi][ni][0], fmaxf(na0 * nb0, EPSV));
            v0.y = __fdividef(acc[mi][ni][1], fmaxf(na0 * nb1, EPSV));
            v1.x = __fdividef(acc[mi][ni][2], fmaxf(na1 * nb0, EPSV));
            v1.y = __fdividef(acc[mi][ni][3], fmaxf(na1 * nb1, EPSV));
            *reinterpret_cast<float2*>(r0 + n0) = v0;
            *reinterpret_cast<float2*>(r1 + n0) = v1;
        }
    }
}

// ---------------- launch ----------------
extern "C" void kernel_launch(void* const* d_in, const int* in_sizes, int n_in,
                              void* d_out, int out_size) {
    const float* x1 = (const float*)d_in[0];  // [8192, 512] -> n rows
    const float* x2 = (const float*)d_in[1];  // [8192, 512] -> m rows
    float* out = (float*)d_out;               // [8192, 8192]

    const int smem_bytes = STAGES * STAGE_ELEMS * 2;  // 61440
    cudaFuncSetAttribute(cosine_mma_kernel,
                         cudaFuncAttributeMaxDynamicSharedMemorySize, smem_bytes);

    prep_kernel<<<NR + MR, 128>>>(x1, x2);

    dim3 grid(NR / BN, MR / BM);  // (64, 64)
    cosine_mma_kernel<<<grid, 256, smem_bytes>>>(out);
}

// round 4
// speedup vs baseline: 2.6725x; 1.0978x over previous
#include <cuda_runtime.h>
#include <cuda_bf16.h>
#include <stdint.h>
#include <math.h>

#define EPSV 1e-8f
#define DD 512
#define MR 8192
#define NR 8192
#define BM 128
#define BN 128
#define BK 64            // bf16 elements per pipeline step
#define PADK 72          // padded smem row (144 B) -> conflict-free ldmatrix
#define STAGES 3
#define SSTEPS 24        // 3 passes (hh, hl, lh) x 8 steps of K=64

// ---------------- device scratch (allocation-free) ----------------
__device__ __nv_bfloat16 g_ah[(size_t)MR * DD];
__device__ __nv_bfloat16 g_al[(size_t)MR * DD];
__device__ __nv_bfloat16 g_bh[(size_t)NR * DD];
__device__ __nv_bfloat16 g_bl[(size_t)NR * DD];
__device__ float g_na[MR];
__device__ float g_nb[NR];

__device__ __forceinline__ uint32_t smem_u32(const void* p) {
    uint32_t a;
    asm("{ .reg .u64 t; cvta.to.shared.u64 t, %1; cvt.u32.u64 %0, t; }" : "=r"(a) : "l"(p));
    return a;
}

#define CP16(dst, src) \
    asm volatile("cp.async.cg.shared.global [%0], [%1], 16;" :: "r"(dst), "l"(src))
#define CP_COMMIT() asm volatile("cp.async.commit_group;" ::: "memory")
#define CP_WAIT(n)  asm volatile("cp.async.wait_group %0;" :: "n"(n) : "memory")

#define LDSM_X4(r0, r1, r2, r3, addr) \
    asm volatile("ldmatrix.sync.aligned.m8n8.x4.shared.b16 {%0,%1,%2,%3}, [%4];" \
                 : "=r"(r0), "=r"(r1), "=r"(r2), "=r"(r3) : "r"(addr))

#define MMA16816(d, a, b0, b1) \
    asm volatile("mma.sync.aligned.m16n8k16.row.col.f32.bf16.bf16.f32 " \
                 "{%0,%1,%2,%3}, {%4,%5,%6,%7}, {%8,%9}, {%0,%1,%2,%3};" \
                 : "+f"((d)[0]), "+f"((d)[1]), "+f"((d)[2]), "+f"((d)[3]) \
                 : "r"((a)[0]), "r"((a)[1]), "r"((a)[2]), "r"((a)[3]), "r"(b0), "r"(b1))

// ---------------- prep: fp32 -> bf16 hi/lo + row norms ----------------
__global__ void prep_kernel(const float* __restrict__ x1, const float* __restrict__ x2) {
    int r = blockIdx.x;
    const float* src;
    __nv_bfloat16 *hi, *lo;
    float* nrm;
    int row;
    if (r < NR) { src = x1; hi = g_bh; lo = g_bl; nrm = g_nb; row = r; }
    else        { src = x2; hi = g_ah; lo = g_al; nrm = g_na; row = r - NR; }

    const float4* p = reinterpret_cast<const float4*>(src + (size_t)row * DD);
    float4 v = p[threadIdx.x];
    float vv[4] = {v.x, v.y, v.z, v.w};
    float s = v.x * v.x + v.y * v.y + v.z * v.z + v.w * v.w;

    __nv_bfloat16 h[4], l[4];
#pragma unroll
    for (int i = 0; i < 4; i++) {
        h[i] = __float2bfloat16(vv[i]);
        l[i] = __float2bfloat16(vv[i] - __bfloat162float(h[i]));
    }
    size_t o = (size_t)row * DD + threadIdx.x * 4;
    *reinterpret_cast<__nv_bfloat162*>(hi + o)     = __halves2bfloat162(h[0], h[1]);
    *reinterpret_cast<__nv_bfloat162*>(hi + o + 2) = __halves2bfloat162(h[2], h[3]);
    *reinterpret_cast<__nv_bfloat162*>(lo + o)     = __halves2bfloat162(l[0], l[1]);
    *reinterpret_cast<__nv_bfloat162*>(lo + o + 2) = __halves2bfloat162(l[2], l[3]);

#pragma unroll
    for (int off = 16; off > 0; off >>= 1)
        s += __shfl_down_sync(0xffffffffu, s, off);
    __shared__ float ws[4];
    if ((threadIdx.x & 31) == 0) ws[threadIdx.x >> 5] = s;
    __syncthreads();
    if (threadIdx.x == 0)
        nrm[row] = sqrtf(ws[0] + ws[1] + ws[2] + ws[3]);
}

// ---------------- GEMM via mma.sync + cosine epilogue ----------------
// Dynamic smem: STAGES stages, each [BM][PADK] A + [BN][PADK] B bf16.
#define STAGE_ELEMS ((BM + BN) * PADK)

__device__ __forceinline__ void load_stage(uint32_t sbase, int stage, int s,
                                           int bm, int bn, int tid) {
    const int pass = s >> 3;            // 0: hh, 1: hl, 2: lh
    const int ko = (s & 7) * BK;
    const __nv_bfloat16* Ap = (pass == 2) ? g_al : g_ah;
    const __nv_bfloat16* Bp = (pass == 1) ? g_bl : g_bh;
    uint32_t abase = sbase + stage * STAGE_ELEMS * 2;
    uint32_t bbase = abase + BM * PADK * 2;
    // A: 128 rows x 128 B = 1024 x 16B chunks (4/thread)
#pragma unroll
    for (int h = 0; h < 4; h++) {
        int c = tid + h * 256;
        int row = c >> 3, seg = c & 7;
        uint32_t dst = abase + (uint32_t)(row * PADK + seg * 8) * 2;
        CP16(dst, Ap + (size_t)(bm + row) * DD + ko + seg * 8);
    }
    // B: 128 rows x 128 B (4/thread)
#pragma unroll
    for (int h = 0; h < 4; h++) {
        int c = tid + h * 256;
        int row = c >> 3, seg = c & 7;
        uint32_t dst = bbase + (uint32_t)(row * PADK + seg * 8) * 2;
        CP16(dst, Bp + (size_t)(bn + row) * DD + ko + seg * 8);
    }
    CP_COMMIT();
}

__global__ void __launch_bounds__(256, 2)
cosine_mma_kernel(float* __restrict__ C) {
    extern __shared__ __align__(16) __nv_bfloat16 smem[];
    const uint32_t sbase = smem_u32(smem);
    const int tid = threadIdx.x;
    const int wid = tid >> 5;
    const int lid = tid & 31;
    const int bm = blockIdx.y * BM;
    const int bn = blockIdx.x * BN;

    __shared__ float s_na[BM], s_nb[BN];
    if (tid < BM) s_na[tid] = g_na[bm + tid];
    else s_nb[tid - BM] = g_nb[bn + tid - BM];

    const int wm = (wid & 1) * 64;   // warp m-base
    const int wn = (wid >> 1) * 32;  // warp n-base

    float acc[4][4][4];
#pragma unroll
    for (int i = 0; i < 4; i++)
#pragma unroll
        for (int j = 0; j < 4; j++)
#pragma unroll
            for (int q = 0; q < 4; q++)
                acc[i][j][q] = 0.0f;

    const int a_row = wm + ((lid >> 3) & 1) * 8 + (lid & 7);
    const int a_kof = ((lid >> 4) & 1) * 8;
    const int b_row = wn + ((lid >> 4) & 1) * 8 + (lid & 7);
    const int b_kof = ((lid >> 3) & 1) * 8;

    // prologue: stages 0, 1 in flight
    load_stage(sbase, 0, 0, bm, bn, tid);
    load_stage(sbase, 1, 1, bm, bn, tid);
    CP_WAIT(1);          // stage 0 complete (per-thread)
    __syncthreads();     // publish

    for (int s = 0; s < SSTEPS; s++) {
        const int stage = s % STAGES;

        // issue loads for stage s+2 (smem slot (s+2)%3 was last read at step
        // s-1; the barrier at the end of step s-1 protects it)
        if (s + STAGES - 1 < SSTEPS)
            load_stage(sbase, (s + STAGES - 1) % STAGES, s + STAGES - 1, bm, bn, tid);

        uint32_t abase = sbase + stage * STAGE_ELEMS * 2;
        uint32_t bbase = abase + BM * PADK * 2;

        // compute stage s: 4 x k16 chunks, overlapped with the loads above
#pragma unroll
        for (int k16 = 0; k16 < BK / 16; k16++) {
            const int k0 = k16 * 16;
            uint32_t a[4][4];
#pragma unroll
            for (int mi = 0; mi < 4; mi++) {
                uint32_t addr = abase + (uint32_t)((a_row + mi * 16) * PADK + k0 + a_kof) * 2;
                LDSM_X4(a[mi][0], a[mi][1], a[mi][2], a[mi][3], addr);
            }
            uint32_t b[2][4];
#pragma unroll
            for (int nj = 0; nj < 2; nj++) {
                uint32_t addr = bbase + (uint32_t)((b_row + nj * 16) * PADK + k0 + b_kof) * 2;
                LDSM_X4(b[nj][0], b[nj][1], b[nj][2], b[nj][3], addr);
            }
#pragma unroll
            for (int mi = 0; mi < 4; mi++)
#pragma unroll
                for (int ni = 0; ni < 4; ni++)
                    MMA16816(acc[mi][ni], a[mi], b[ni >> 1][(ni & 1) * 2],
                             b[ni >> 1][(ni & 1) * 2 + 1]);
        }

        // next stage (s+1) must be resident before the next iteration reads it
        CP_WAIT(1);
        __syncthreads();
    }

    // epilogue: cosine divide + store
    const int qrow = lid >> 2;
    const int qcol = (lid & 3) * 2;
#pragma unroll
    for (int mi = 0; mi < 4; mi++) {
        int m0 = wm + mi * 16 + qrow;
        float na0 = s_na[m0];
        float na1 = s_na[m0 + 8];
        float* r0 = C + (size_t)(bm + m0) * NR + bn;
        float* r1 = C + (size_t)(bm + m0 + 8) * NR + bn;
#pragma unroll
        for (int ni = 0; ni < 4; ni++) {
            int n0 = wn + ni * 8 + qcol;
            float nb0 = s_nb[n0], nb1 = s_nb[n0 + 1];
            float2 v0, v1;
            v0.x = __fdividef(acc[mi][ni][0], fmaxf(na0 * nb0, EPSV));
            v0.y = __fdividef(acc[mi][ni][1], fmaxf(na0 * nb1, EPSV));
            v1.x = __fdividef(acc[mi][ni][2], fmaxf(na1 * nb0, EPSV));
            v1.y = __fdividef(acc[mi][ni][3], fmaxf(na1 * nb1, EPSV));
            *reinterpret_cast<float2*>(r0 + n0) = v0;
            *reinterpret_cast<float2*>(r1 + n0) = v1;
        }
    }
}

// ---------------- launch ----------------
extern "C" void kernel_launch(void* const* d_in, const int* in_sizes, int n_in,
                              void* d_out, int out_size) {
    const float* x1 = (const float*)d_in[0];  // [8192, 512] -> n rows
    const float* x2 = (const float*)d_in[1];  // [8192, 512] -> m rows
    float* out = (float*)d_out;               // [8192, 8192]

    const int smem_bytes = STAGES * STAGE_ELEMS * 2;  // 110592
    cudaFuncSetAttribute(cosine_mma_kernel,
                         cudaFuncAttributeMaxDynamicSharedMemorySize, smem_bytes);

    prep_kernel<<<NR + MR, 128>>>(x1, x2);

    dim3 grid(NR / BN, MR / BM);  // (64, 64)
    cosine_mma_kernel<<<grid, 256, smem_bytes>>>(out);
}